// round 15
// baseline (speedup 1.0000x reference)
#include <cuda_runtime.h>
#include <cstdint>

// ---------------- problem constants ----------------
constexpr int B    = 32768;
constexpr int S    = 40;            // feature groups (5 features each)
constexpr int FPG  = 5;             // features per group
constexpr int FC   = 5;             // features per smem chunk
constexpr int NCH  = FPG / FC;      // 1

constexpr int TPB  = 128;
constexpr int RB   = 128;           // row CTAs
constexpr int GRID = S * RB;        // 5120
constexpr int HALF = RB * TPB;      // 16384 (R=2: rowB = rowA + HALF; exact cover)

constexpr int YPITCH = 25;          // odd -> conflict-free

// ---------------- smem layout (float offsets; vector regions 16B-aligned) ----------------
constexpr int OFF_YA = 0;                        // [128][25]
constexpr int OFF_YB = OFF_YA + TPB * YPITCH;    // 3200
constexpr int OFF_W1 = OFF_YB + TPB * YPITCH;    // 6400  [f][d][16]
constexpr int OFF_B1 = OFF_W1 + FC * 80;         // 6800  [f][16]
constexpr int OFF_W2 = OFF_B1 + FC * 16;         // 6880  [f][h][32]
constexpr int OFF_B2 = OFF_W2 + FC * 480;        // 9280  [f][32] (o>=30 -> 0)
constexpr int OFF_W3 = OFF_B2 + FC * 32;         // 9440  [f][32] (o>=30 -> 0)
constexpr int SMEM_FLOATS = OFF_W3 + FC * 32;    // 9600 -> 38400 B static (x6 CTAs fits carveout)

typedef unsigned long long u64;

__device__ __forceinline__ u64 pack2(float lo, float hi) {
    u64 r; asm("mov.b64 %0, {%1, %2};" : "=l"(r) : "f"(lo), "f"(hi)); return r;
}
__device__ __forceinline__ void unpack2(u64 v, float& lo, float& hi) {
    asm("mov.b64 {%0, %1}, %2;" : "=f"(lo), "=f"(hi) : "l"(v));
}
__device__ __forceinline__ void fma2(u64& d, u64 a, u64 b) {
    asm("fma.rn.f32x2 %0, %1, %2, %0;" : "+l"(d) : "l"(a), "l"(b));
}
// packed relu via scalar FMNMX on the halves (alu pipe); pack/unpack movs coalesce
__device__ __forceinline__ u64 relu2(u64 a) {
    float lo, hi;
    unpack2(a, lo, hi);
    return pack2(fmaxf(lo, 0.f), fmaxf(hi, 0.f));
}

__global__ void init_out_kernel(const float* __restrict__ b3, float* __restrict__ out) {
    int i = blockIdx.x * blockDim.x + threadIdx.x;
    out[i] = __ldg(b3);
}

// Layer-2 pass over outputs [P0, P0 + 2*NU): NU packed accumulators per row.
// Epilogue packed: relu2 halves + one fma2 per output pair into packed accs.
template<int P0, int NU>
__device__ __forceinline__ void l2pass(const float* __restrict__ smem, int fl,
                                       const float* __restrict__ hA, const float* __restrict__ hB,
                                       u64& accPA0, u64& accPA1, u64& accPB0, u64& accPB1)
{
    u64 sA[NU], sB[NU];
    {
        const float* bsrc = &smem[OFF_B2 + fl * 32 + P0];
        #pragma unroll
        for (int i = 0; i < NU / 2; ++i) {
            ulonglong2 v = reinterpret_cast<const ulonglong2*>(bsrc)[i];
            sA[2*i] = v.x; sA[2*i+1] = v.y;
            sB[2*i] = v.x; sB[2*i+1] = v.y;
        }
        if (NU & 1) {
            u64 v = reinterpret_cast<const u64*>(bsrc)[NU - 1];
            sA[NU-1] = v; sB[NU-1] = v;
        }
    }
    #pragma unroll
    for (int h = 0; h < 15; ++h) {
        u64 hhA = pack2(hA[h], hA[h]);
        u64 hhB = pack2(hB[h], hB[h]);
        const float* wsrc = &smem[OFF_W2 + fl * 480 + h * 32 + P0];
        #pragma unroll
        for (int i = 0; i < NU / 2; ++i) {
            ulonglong2 v = reinterpret_cast<const ulonglong2*>(wsrc)[i];
            fma2(sA[2*i],   v.x, hhA);
            fma2(sA[2*i+1], v.y, hhA);
            fma2(sB[2*i],   v.x, hhB);
            fma2(sB[2*i+1], v.y, hhB);
        }
        if (NU & 1) {
            u64 v = reinterpret_cast<const u64*>(wsrc)[NU - 1];
            fma2(sA[NU-1], v, hhA);
            fma2(sB[NU-1], v, hhB);
        }
    }
    // packed epilogue: relu halves + packed w3 fma2 (w3 in natural (w[2o], w[2o+1]) pairs)
    const u64* w3p = reinterpret_cast<const u64*>(&smem[OFF_W3 + fl * 32 + P0]);
    #pragma unroll
    for (int i = 0; i < NU; ++i) {
        u64 w = w3p[i];
        if (i & 1) {
            fma2(accPA1, relu2(sA[i]), w);
            fma2(accPB1, relu2(sB[i]), w);
        } else {
            fma2(accPA0, relu2(sA[i]), w);
            fma2(accPB0, relu2(sB[i]), w);
        }
    }
}

__global__ __launch_bounds__(TPB, 6)
void mlp_fused_kernel(const float* __restrict__ y,
                      const float* __restrict__ W1,
                      const float* __restrict__ b1,
                      const float* __restrict__ W2,
                      const float* __restrict__ b2,
                      const float* __restrict__ W3,
                      float* __restrict__ out)
{
    __shared__ float smem[SMEM_FLOATS];

    const int tid = threadIdx.x;
    const int bq  = blockIdx.x >> 7;        // feature group 0..39
    const int br  = blockIdx.x & 127;       // row CTA 0..127

    const int rowA = br * TPB + tid;        // < 16384
    const int rowB = rowA + HALF;           // < 32768 (exact, no clamp)

    u64 accPA0 = 0, accPA1 = 0, accPB0 = 0, accPB1 = 0;

    #pragma unroll 1
    for (int c = 0; c < NCH; ++c) {
        const int f0 = bq * FPG + c * FC;

        __syncthreads();

        // ---- stage y tiles (coalesced 100B row segments), both row sets ----
        for (int i = tid; i < TPB * 25; i += TPB) {
            int r = i / 25, cc = i % 25;
            smem[OFF_YA + i] = __ldg(y + (size_t)(br * TPB + r) * 1000 + f0 * 5 + cc);
            smem[OFF_YB + i] = __ldg(y + (size_t)(br * TPB + r + HALF) * 1000 + f0 * 5 + cc);
        }
        // ---- stage weights (padded layouts) ----
        for (int i = tid; i < FC * 75; i += TPB) {
            int f = i / 75, r = i % 75, d = r / 15, h = r % 15;
            smem[OFF_W1 + f * 80 + d * 16 + h] = W1[f0 * 75 + i];
        }
        for (int i = tid; i < FC * 15; i += TPB) {
            int f = i / 15, h = i % 15;
            smem[OFF_B1 + f * 16 + h] = b1[f0 * 15 + i];
        }
        for (int i = tid; i < FC * 450; i += TPB) {
            int f = i / 450, r = i % 450, h = r / 30, o = r % 30;
            smem[OFF_W2 + f * 480 + h * 32 + o] = W2[f0 * 450 + i];
        }
        for (int i = tid; i < FC * 30; i += TPB) {
            int f = i / 30, o = i % 30;
            smem[OFF_B2 + f * 32 + o] = b2[f0 * 30 + i];
            smem[OFF_W3 + f * 32 + o] = W3[f0 * 30 + i];
        }
        // zero padding lanes (o = 30, 31) so packed epilogue pairs are exact
        for (int i = tid; i < FC * 2; i += TPB) {
            int f = i >> 1, o = 30 + (i & 1);
            smem[OFF_W3 + f * 32 + o] = 0.f;
            smem[OFF_B2 + f * 32 + o] = 0.f;
        }
        __syncthreads();

        #pragma unroll 1
        for (int fl = 0; fl < FC; ++fl) {
            // ---- y from smem (pitch 25 -> conflict-free) ----
            const float* yAp = &smem[OFF_YA + tid * YPITCH + fl * 5];
            const float* yBp = &smem[OFF_YB + tid * YPITCH + fl * 5];
            u64 ydA[5], ydB[5];
            #pragma unroll
            for (int d = 0; d < 5; ++d) {
                float va = yAp[d], vb = yBp[d];
                ydA[d] = pack2(va, va);
                ydB[d] = pack2(vb, vb);
            }

            // ---- layer 1 (packed): 8 pairs; pair-7 hi = padding, never consumed ----
            u64 h1A[8], h1B[8];
            {
                const ulonglong2* bv = reinterpret_cast<const ulonglong2*>(&smem[OFF_B1 + fl * 16]);
                #pragma unroll
                for (int j = 0; j < 4; ++j) {
                    ulonglong2 v = bv[j];
                    h1A[2*j] = v.x; h1A[2*j+1] = v.y;
                    h1B[2*j] = v.x; h1B[2*j+1] = v.y;
                }
            }
            #pragma unroll
            for (int d = 0; d < 5; ++d) {
                const ulonglong2* wv = reinterpret_cast<const ulonglong2*>(&smem[OFF_W1 + fl * 80 + d * 16]);
                #pragma unroll
                for (int j = 0; j < 4; ++j) {
                    ulonglong2 v = wv[j];
                    fma2(h1A[2*j],   v.x, ydA[d]);
                    fma2(h1A[2*j+1], v.y, ydA[d]);
                    fma2(h1B[2*j],   v.x, ydB[d]);
                    fma2(h1B[2*j+1], v.y, ydB[d]);
                }
            }

            float hA[16], hB[16];
            #pragma unroll
            for (int j = 0; j < 8; ++j) {
                unpack2(h1A[j], hA[2*j], hA[2*j+1]);
                unpack2(h1B[j], hB[2*j], hB[2*j+1]);
            }

            // ---- layer 2 in four register-light passes: [0,8), [8,16), [16,24), [24,30) ----
            l2pass< 0, 4>(smem, fl, hA, hB, accPA0, accPA1, accPB0, accPB1);
            l2pass< 8, 4>(smem, fl, hA, hB, accPA0, accPA1, accPB0, accPB1);
            l2pass<16, 4>(smem, fl, hA, hB, accPA0, accPA1, accPB0, accPB1);
            l2pass<24, 3>(smem, fl, hA, hB, accPA0, accPA1, accPB0, accPB1);
        }
    }

    // unpack packed accumulators once; combine feature-group partials (out pre-set to b3)
    float a0, a1, a2, a3;
    unpack2(accPA0, a0, a1);
    unpack2(accPA1, a2, a3);
    atomicAdd(out + rowA, (a0 + a1) + (a2 + a3));
    unpack2(accPB0, a0, a1);
    unpack2(accPB1, a2, a3);
    atomicAdd(out + rowB, (a0 + a1) + (a2 + a3));
}

extern "C" void kernel_launch(void* const* d_in, const int* in_sizes, int n_in,
                              void* d_out, int out_size)
{
    const float* y  = (const float*)d_in[0];
    const float* W1 = (const float*)d_in[1];
    const float* b1 = (const float*)d_in[2];
    const float* W2 = (const float*)d_in[3];
    const float* b2 = (const float*)d_in[4];
    const float* W3 = (const float*)d_in[5];
    const float* b3 = (const float*)d_in[6];
    float* out = (float*)d_out;

    init_out_kernel<<<B / 256, 256>>>(b3, out);
    mlp_fused_kernel<<<GRID, TPB>>>(y, W1, b1, W2, b2, W3, out);
}

// round 16
// speedup vs baseline: 1.0375x; 1.0375x over previous
#include <cuda_runtime.h>
#include <cstdint>

// ---------------- problem constants ----------------
constexpr int B    = 32768;
constexpr int S    = 40;            // feature groups (5 features each)
constexpr int FPG  = 5;             // features per group
constexpr int FC   = 5;             // features per smem chunk
constexpr int NCH  = FPG / FC;      // 1

constexpr int TPB  = 128;
constexpr int RB   = 128;           // row CTAs
constexpr int GRID = S * RB;        // 5120
constexpr int HALF = RB * TPB;      // 16384 (R=2: rowB = rowA + HALF; exact cover)

constexpr int YPITCH = 25;          // odd -> conflict-free

// ---------------- smem layout (float offsets; vector regions 16B-aligned) ----------------
constexpr int OFF_YA = 0;                        // [128][25]
constexpr int OFF_YB = OFF_YA + TPB * YPITCH;    // 3200
constexpr int OFF_W1 = OFF_YB + TPB * YPITCH;    // 6400  [f][d][16]
constexpr int OFF_B1 = OFF_W1 + FC * 80;         // 6800  [f][16]
constexpr int OFF_W2 = OFF_B1 + FC * 16;         // 6880  [f][h][32]
constexpr int OFF_B2 = OFF_W2 + FC * 480;        // 9280  [f][32]
constexpr int OFF_W3 = OFF_B2 + FC * 32;         // 9440  [f][32]
constexpr int SMEM_FLOATS = OFF_W3 + FC * 32;    // 9600 -> 38400 B static (x6 CTAs fits carveout)

typedef unsigned long long u64;

__device__ __forceinline__ u64 pack2(float lo, float hi) {
    u64 r; asm("mov.b64 %0, {%1, %2};" : "=l"(r) : "f"(lo), "f"(hi)); return r;
}
__device__ __forceinline__ void unpack2(u64 v, float& lo, float& hi) {
    asm("mov.b64 {%0, %1}, %2;" : "=f"(lo), "=f"(hi) : "l"(v));
}
__device__ __forceinline__ void fma2(u64& d, u64 a, u64 b) {
    asm("fma.rn.f32x2 %0, %1, %2, %0;" : "+l"(d) : "l"(a), "l"(b));
}

__global__ void init_out_kernel(const float* __restrict__ b3, float* __restrict__ out) {
    int i = blockIdx.x * blockDim.x + threadIdx.x;
    out[i] = __ldg(b3);
}

// Layer-2 pass over outputs [P0, P0 + 2*NU): NU u64 accumulators per row.
template<int P0, int NU>
__device__ __forceinline__ void l2pass(const float* __restrict__ smem, int fl,
                                       const float* __restrict__ hA, const float* __restrict__ hB,
                                       float& accA0, float& accA1, float& accB0, float& accB1)
{
    u64 sA[NU], sB[NU];
    {
        const float* bsrc = &smem[OFF_B2 + fl * 32 + P0];
        #pragma unroll
        for (int i = 0; i < NU / 2; ++i) {
            ulonglong2 v = reinterpret_cast<const ulonglong2*>(bsrc)[i];
            sA[2*i] = v.x; sA[2*i+1] = v.y;
            sB[2*i] = v.x; sB[2*i+1] = v.y;
        }
        if (NU & 1) {
            u64 v = reinterpret_cast<const u64*>(bsrc)[NU - 1];
            sA[NU-1] = v; sB[NU-1] = v;
        }
    }
    #pragma unroll
    for (int h = 0; h < 15; ++h) {
        u64 hhA = pack2(hA[h], hA[h]);
        u64 hhB = pack2(hB[h], hB[h]);
        const float* wsrc = &smem[OFF_W2 + fl * 480 + h * 32 + P0];
        #pragma unroll
        for (int i = 0; i < NU / 2; ++i) {
            ulonglong2 v = reinterpret_cast<const ulonglong2*>(wsrc)[i];
            fma2(sA[2*i],   v.x, hhA);
            fma2(sA[2*i+1], v.y, hhA);
            fma2(sB[2*i],   v.x, hhB);
            fma2(sB[2*i+1], v.y, hhB);
        }
        if (NU & 1) {
            u64 v = reinterpret_cast<const u64*>(wsrc)[NU - 1];
            fma2(sA[NU-1], v, hhA);
            fma2(sB[NU-1], v, hhB);
        }
    }
    const float2* w3p = reinterpret_cast<const float2*>(&smem[OFF_W3 + fl * 32 + P0]);
    #pragma unroll
    for (int i = 0; i < NU; ++i) {
        float2 w = w3p[i];
        float x0, x1, z0, z1;
        unpack2(sA[i], x0, x1);
        unpack2(sB[i], z0, z1);
        accA0 = fmaf(fmaxf(x0, 0.f), w.x, accA0);
        accA1 = fmaf(fmaxf(x1, 0.f), w.y, accA1);
        accB0 = fmaf(fmaxf(z0, 0.f), w.x, accB0);
        accB1 = fmaf(fmaxf(z1, 0.f), w.y, accB1);
    }
}

__global__ __launch_bounds__(TPB, 6)
void mlp_fused_kernel(const float* __restrict__ y,
                      const float* __restrict__ W1,
                      const float* __restrict__ b1,
                      const float* __restrict__ W2,
                      const float* __restrict__ b2,
                      const float* __restrict__ W3,
                      float* __restrict__ out)
{
    __shared__ float smem[SMEM_FLOATS];

    const int tid = threadIdx.x;
    const int bq  = blockIdx.x >> 7;        // feature group 0..39
    const int br  = blockIdx.x & 127;       // row CTA 0..127

    const int rowA = br * TPB + tid;        // < 16384
    const int rowB = rowA + HALF;           // < 32768 (exact, no clamp)

    float accA0 = 0.f, accA1 = 0.f, accB0 = 0.f, accB1 = 0.f;

    #pragma unroll 1
    for (int c = 0; c < NCH; ++c) {
        const int f0 = bq * FPG + c * FC;

        __syncthreads();

        // ---- stage y tiles (coalesced 100B row segments), both row sets ----
        for (int i = tid; i < TPB * 25; i += TPB) {
            int r = i / 25, cc = i % 25;
            smem[OFF_YA + i] = __ldg(y + (size_t)(br * TPB + r) * 1000 + f0 * 5 + cc);
            smem[OFF_YB + i] = __ldg(y + (size_t)(br * TPB + r + HALF) * 1000 + f0 * 5 + cc);
        }
        // ---- stage weights (padded layouts) ----
        for (int i = tid; i < FC * 75; i += TPB) {
            int f = i / 75, r = i % 75, d = r / 15, h = r % 15;
            smem[OFF_W1 + f * 80 + d * 16 + h] = W1[f0 * 75 + i];
        }
        for (int i = tid; i < FC * 15; i += TPB) {
            int f = i / 15, h = i % 15;
            smem[OFF_B1 + f * 16 + h] = b1[f0 * 15 + i];
        }
        for (int i = tid; i < FC * 450; i += TPB) {
            int f = i / 450, r = i % 450, h = r / 30, o = r % 30;
            smem[OFF_W2 + f * 480 + h * 32 + o] = W2[f0 * 450 + i];
        }
        for (int i = tid; i < FC * 30; i += TPB) {
            int f = i / 30, o = i % 30;
            smem[OFF_B2 + f * 32 + o] = b2[f0 * 30 + i];
            smem[OFF_W3 + f * 32 + o] = W3[f0 * 30 + i];
        }
        __syncthreads();

        #pragma unroll 1
        for (int fl = 0; fl < FC; ++fl) {
            // ---- y from smem (pitch 25 -> conflict-free) ----
            const float* yAp = &smem[OFF_YA + tid * YPITCH + fl * 5];
            const float* yBp = &smem[OFF_YB + tid * YPITCH + fl * 5];
            u64 ydA[5], ydB[5];
            #pragma unroll
            for (int d = 0; d < 5; ++d) {
                float va = yAp[d], vb = yBp[d];
                ydA[d] = pack2(va, va);
                ydB[d] = pack2(vb, vb);
            }

            // ---- layer 1 (packed): 8 pairs; pair-7 hi = padding, never consumed ----
            u64 h1A[8], h1B[8];
            {
                const ulonglong2* bv = reinterpret_cast<const ulonglong2*>(&smem[OFF_B1 + fl * 16]);
                #pragma unroll
                for (int j = 0; j < 4; ++j) {
                    ulonglong2 v = bv[j];
                    h1A[2*j] = v.x; h1A[2*j+1] = v.y;
                    h1B[2*j] = v.x; h1B[2*j+1] = v.y;
                }
            }
            #pragma unroll
            for (int d = 0; d < 5; ++d) {
                const ulonglong2* wv = reinterpret_cast<const ulonglong2*>(&smem[OFF_W1 + fl * 80 + d * 16]);
                #pragma unroll
                for (int j = 0; j < 4; ++j) {
                    ulonglong2 v = wv[j];
                    fma2(h1A[2*j],   v.x, ydA[d]);
                    fma2(h1A[2*j+1], v.y, ydA[d]);
                    fma2(h1B[2*j],   v.x, ydB[d]);
                    fma2(h1B[2*j+1], v.y, ydB[d]);
                }
            }

            float hA[16], hB[16];
            #pragma unroll
            for (int j = 0; j < 8; ++j) {
                unpack2(h1A[j], hA[2*j], hA[2*j+1]);
                unpack2(h1B[j], hB[2*j], hB[2*j+1]);
            }

            // ---- layer 2 in three passes: outputs [0,12), [12,24), [24,30) ----
            l2pass< 0, 6>(smem, fl, hA, hB, accA0, accA1, accB0, accB1);
            l2pass<12, 6>(smem, fl, hA, hB, accA0, accA1, accB0, accB1);
            l2pass<24, 3>(smem, fl, hA, hB, accA0, accA1, accB0, accB1);
        }
    }

    // combine feature-group partials; out pre-initialized to b3
    atomicAdd(out + rowA, accA0 + accA1);
    atomicAdd(out + rowB, accB0 + accB1);
}

extern "C" void kernel_launch(void* const* d_in, const int* in_sizes, int n_in,
                              void* d_out, int out_size)
{
    const float* y  = (const float*)d_in[0];
    const float* W1 = (const float*)d_in[1];
    const float* b1 = (const float*)d_in[2];
    const float* W2 = (const float*)d_in[3];
    const float* b2 = (const float*)d_in[4];
    const float* W3 = (const float*)d_in[5];
    const float* b3 = (const float*)d_in[6];
    float* out = (float*)d_out;

    init_out_kernel<<<B / 256, 256>>>(b3, out);
    mlp_fused_kernel<<<GRID, TPB>>>(y, W1, b1, W2, b2, W3, out);
}